// round 2
// baseline (speedup 1.0000x reference)
#include <cuda_runtime.h>

// Problem shape (fixed by reference):
//   x: [8, 256, 256, 256] fp32 ; W: [256,256] ; b: [256]
//   u = x[:, :128], v = x[:, 128:]
//   per-batch LayerNorm of v over all non-batch dims, then v @ W^T + b,
//   out = u * (v + 1)
#define B_              8
#define CH              128
#define G_              256
#define WD              256
#define ROWS_PER_BATCH  (CH * G_)            // 32768
#define M_TOTAL         (B_ * ROWS_PER_BATCH) // 262144
#define NV              (ROWS_PER_BATCH * WD) // 8388608 elements of v per batch
#define BATCH_STRIDE    (2 * NV)             // x elements per batch
#define NCHUNK          512
#define EPS             1e-5f

// GEMM tiling
#define BM 64
#define BN 256
#define BK 32
#define AS_STRIDE 68    // 64 + 4 pad (keeps 16B alignment: 68*4 = 272 = 17*16)
#define BS_STRIDE 260   // 256 + 4 pad (1040 = 65*16)

// ---------------- device scratch (no allocations allowed) ----------------
__device__ float g_partS[B_ * NCHUNK];
__device__ float g_partQ[B_ * NCHUNK];
__device__ float g_mean[B_];
__device__ float g_rstd[B_];

// ---------------- f32x2 helpers (Blackwell packed fp32 FMA) ----------------
__device__ __forceinline__ unsigned long long dup_f32x2(float x) {
    unsigned long long r;
    unsigned int xi = __float_as_uint(x);
    asm("mov.b64 %0, {%1, %1};" : "=l"(r) : "r"(xi));
    return r;
}
__device__ __forceinline__ void fma_f32x2(unsigned long long& d,
                                          unsigned long long a,
                                          unsigned long long b) {
    asm("fma.rn.f32x2 %0, %1, %2, %0;" : "+l"(d) : "l"(a), "l"(b));
}
__device__ __forceinline__ float2 unpack_f32x2(unsigned long long v) {
    float2 r;
    asm("mov.b64 {%0, %1}, %2;" : "=f"(r.x), "=f"(r.y) : "l"(v));
    return r;
}

// XOR swizzle of the m index (groups of 8) by k-group — kills the 16-way
// bank conflict in the A-tile transpose staging while keeping mainloop
// reads conflict-free (swizzle is constant per k-row; float4 alignment kept
// because the swizzle term is a multiple of 8).
__device__ __forceinline__ int a_swz(int k) { return ((k >> 2) & 7) * 8; }

// ---------------- pass 1: per-(batch,chunk) partial sum / sumsq of v -------
__global__ __launch_bounds__(256) void reduce_pass1(const float* __restrict__ x) {
    const int b = blockIdx.y;
    const int chunk = blockIdx.x;
    const float4* v4 =
        reinterpret_cast<const float4*>(x + (size_t)b * BATCH_STRIDE + NV);
    const int base = chunk * 4096 + threadIdx.x;

    float s = 0.f, q = 0.f;
#pragma unroll
    for (int i = 0; i < 16; i++) {
        float4 t = v4[base + i * 256];
        s += (t.x + t.y) + (t.z + t.w);
        q += t.x * t.x + t.y * t.y + t.z * t.z + t.w * t.w;
    }
#pragma unroll
    for (int off = 16; off > 0; off >>= 1) {
        s += __shfl_xor_sync(0xffffffffu, s, off);
        q += __shfl_xor_sync(0xffffffffu, q, off);
    }
    __shared__ float ss[8], qs[8];
    const int warp = threadIdx.x >> 5, lane = threadIdx.x & 31;
    if (lane == 0) { ss[warp] = s; qs[warp] = q; }
    __syncthreads();
    if (threadIdx.x == 0) {
        float S = 0.f, Q = 0.f;
#pragma unroll
        for (int w = 0; w < 8; w++) { S += ss[w]; Q += qs[w]; }
        g_partS[b * NCHUNK + chunk] = S;
        g_partQ[b * NCHUNK + chunk] = Q;
    }
}

// ---------------- pass 2: finalize mean / rstd per batch -------------------
__global__ __launch_bounds__(256) void reduce_pass2() {
    const int b = blockIdx.x;
    float s = g_partS[b * NCHUNK + threadIdx.x] +
              g_partS[b * NCHUNK + 256 + threadIdx.x];
    float q = g_partQ[b * NCHUNK + threadIdx.x] +
              g_partQ[b * NCHUNK + 256 + threadIdx.x];
#pragma unroll
    for (int off = 16; off > 0; off >>= 1) {
        s += __shfl_xor_sync(0xffffffffu, s, off);
        q += __shfl_xor_sync(0xffffffffu, q, off);
    }
    __shared__ float ss[8], qs[8];
    const int warp = threadIdx.x >> 5, lane = threadIdx.x & 31;
    if (lane == 0) { ss[warp] = s; qs[warp] = q; }
    __syncthreads();
    if (threadIdx.x == 0) {
        float S = 0.f, Q = 0.f;
#pragma unroll
        for (int w = 0; w < 8; w++) { S += ss[w]; Q += qs[w]; }
        const float inv_n = 1.0f / (float)NV;
        float mean = S * inv_n;
        float var = Q * inv_n - mean * mean;
        g_mean[b] = mean;
        g_rstd[b] = rsqrtf(var + EPS);
    }
}

// ---------------- pass 3: fused normalize + GEMM + gating ------------------
// Block: 64 rows x 256 outputs, 256 threads, each thread 8x8 outputs.
// Warp layout: warp = wm(2) x wo(4) over 32x64 warp tiles;
// lane = mw(4) x ow(8); thread tile m0 = wm*32 + mw*8, o0 = wo*64 + ow*8.
extern __shared__ float smem3[];

__global__ __launch_bounds__(256, 1) void fused_kernel(
    const float* __restrict__ x, const float* __restrict__ W,
    const float* __restrict__ bias, float* __restrict__ out) {
    float* As = smem3;                       // [256][AS_STRIDE] normalized v^T
    float* Bs = As + 256 * AS_STRIDE;        // [2][BK][BS_STRIDE] W^T chunks
    float* bias_s = Bs + 2 * BK * BS_STRIDE; // [256]

    const int t = threadIdx.x;
    const int row0 = blockIdx.x * BM;
    const int batch = row0 >> 15;            // 32768 rows per batch
    const float mean = g_mean[batch];
    const float rstd = g_rstd[batch];

    // ---- load + normalize A tile (64x256), store transposed As[k][m^swz] --
    {
        const float4* v4 = reinterpret_cast<const float4*>(
            x + (size_t)row0 * WD + (size_t)(batch + 1) * NV);
#pragma unroll
        for (int i = 0; i < 16; i++) {
            int idx4 = i * 256 + t;
            int m = idx4 >> 6;       // 64 float4 per row
            int k = (idx4 & 63) * 4;
            int ms = m ^ a_swz(k);   // same swizzle group for k..k+3
            float4 val = v4[idx4];
            val.x = (val.x - mean) * rstd;
            val.y = (val.y - mean) * rstd;
            val.z = (val.z - mean) * rstd;
            val.w = (val.w - mean) * rstd;
            As[(k + 0) * AS_STRIDE + ms] = val.x;
            As[(k + 1) * AS_STRIDE + ms] = val.y;
            As[(k + 2) * AS_STRIDE + ms] = val.z;
            As[(k + 3) * AS_STRIDE + ms] = val.w;
        }
    }
    if (t < 64)
        reinterpret_cast<float4*>(bias_s)[t] =
            reinterpret_cast<const float4*>(bias)[t];

    const float4* W4 = reinterpret_cast<const float4*>(W);

    // ---- load W chunk 0 into Bs[0][kk][o] (transposed) ----
#pragma unroll
    for (int i = 0; i < 8; i++) {
        int idx = i * 256 + t;   // 2048 float4 per chunk
        int o = idx >> 3;
        int kk4 = idx & 7;
        float4 wv = W4[o * 64 + kk4];
        int kk = kk4 * 4;
        Bs[(kk + 0) * BS_STRIDE + o] = wv.x;
        Bs[(kk + 1) * BS_STRIDE + o] = wv.y;
        Bs[(kk + 2) * BS_STRIDE + o] = wv.z;
        Bs[(kk + 3) * BS_STRIDE + o] = wv.w;
    }
    __syncthreads();

    const int wid = t >> 5, lane = t & 31;
    const int m0 = (wid >> 2) * 32 + (lane >> 3) * 8;
    const int o0 = (wid & 3) * 64 + (lane & 7) * 8;

    unsigned long long acc[8][4];
#pragma unroll
    for (int i = 0; i < 8; i++)
#pragma unroll
        for (int j = 0; j < 4; j++) acc[i][j] = 0ull;

#pragma unroll 1
    for (int c = 0; c < 8; c++) {
        const int buf = c & 1;

        // prefetch next W chunk to registers (overlaps with compute)
        float4 pf[8];
        if (c < 7) {
#pragma unroll
            for (int i = 0; i < 8; i++) {
                int idx = i * 256 + t;
                int o = idx >> 3;
                int kk4 = idx & 7;
                pf[i] = W4[o * 64 + (c + 1) * 8 + kk4];
            }
        }

        // compute on chunk c
#pragma unroll
        for (int kk = 0; kk < BK; kk++) {
            const int k = c * BK + kk;
            const float* arow = &As[k * AS_STRIDE + (m0 ^ a_swz(k))];
            float4 a0 = *reinterpret_cast<const float4*>(arow);
            float4 a1 = *reinterpret_cast<const float4*>(arow + 4);
            const float* brow = &Bs[(buf * BK + kk) * BS_STRIDE + o0];
            ulonglong2 b01 = *reinterpret_cast<const ulonglong2*>(brow);
            ulonglong2 b23 = *reinterpret_cast<const ulonglong2*>(brow + 4);
            unsigned long long bb0 = b01.x, bb1 = b01.y, bb2 = b23.x, bb3 = b23.y;
            float a[8] = {a0.x, a0.y, a0.z, a0.w, a1.x, a1.y, a1.z, a1.w};
#pragma unroll
            for (int i = 0; i < 8; i++) {
                unsigned long long aa = dup_f32x2(a[i]);
                fma_f32x2(acc[i][0], aa, bb0);
                fma_f32x2(acc[i][1], aa, bb1);
                fma_f32x2(acc[i][2], aa, bb2);
                fma_f32x2(acc[i][3], aa, bb3);
            }
        }

        // stage next chunk into the other buffer
        if (c < 7) {
            const int nb = (c + 1) & 1;
#pragma unroll
            for (int i = 0; i < 8; i++) {
                int idx = i * 256 + t;
                int o = idx >> 3;
                int kk = (idx & 7) * 4;
                Bs[(nb * BK + kk + 0) * BS_STRIDE + o] = pf[i].x;
                Bs[(nb * BK + kk + 1) * BS_STRIDE + o] = pf[i].y;
                Bs[(nb * BK + kk + 2) * BS_STRIDE + o] = pf[i].z;
                Bs[(nb * BK + kk + 3) * BS_STRIDE + o] = pf[i].w;
            }
            __syncthreads();
        }
    }

    // ---- epilogue: out = u * (acc + bias + 1) ----
#pragma unroll
    for (int i = 0; i < 8; i++) {
        const int r = row0 + m0 + i;
        const float* up = x + (size_t)r * WD + (size_t)batch * NV + o0;
        float* op = out + (size_t)r * WD + o0;
        float4 u0 = *reinterpret_cast<const float4*>(up);
        float4 u1 = *reinterpret_cast<const float4*>(up + 4);
        float4 bz0 = *reinterpret_cast<const float4*>(&bias_s[o0]);
        float4 bz1 = *reinterpret_cast<const float4*>(&bias_s[o0 + 4]);
        float2 p0 = unpack_f32x2(acc[i][0]);
        float2 p1 = unpack_f32x2(acc[i][1]);
        float2 p2 = unpack_f32x2(acc[i][2]);
        float2 p3 = unpack_f32x2(acc[i][3]);
        float4 r0, r1;
        r0.x = u0.x * (p0.x + bz0.x + 1.f);
        r0.y = u0.y * (p0.y + bz0.y + 1.f);
        r0.z = u0.z * (p1.x + bz0.z + 1.f);
        r0.w = u0.w * (p1.y + bz0.w + 1.f);
        r1.x = u1.x * (p2.x + bz1.x + 1.f);
        r1.y = u1.y * (p2.y + bz1.y + 1.f);
        r1.z = u1.z * (p3.x + bz1.z + 1.f);
        r1.w = u1.w * (p3.y + bz1.w + 1.f);
        *reinterpret_cast<float4*>(op) = r0;
        *reinterpret_cast<float4*>(op + 4) = r1;
    }
}

// ---------------- launch ----------------------------------------------------
extern "C" void kernel_launch(void* const* d_in, const int* in_sizes, int n_in,
                              void* d_out, int out_size) {
    const float* x = (const float*)d_in[0];
    const float* W = (const float*)d_in[1];
    const float* b = (const float*)d_in[2];
    float* out = (float*)d_out;

    reduce_pass1<<<dim3(NCHUNK, B_), 256>>>(x);
    reduce_pass2<<<B_, 256>>>();

    const size_t smem_bytes =
        (size_t)(256 * AS_STRIDE + 2 * BK * BS_STRIDE + 256) * sizeof(float);
    cudaFuncSetAttribute(fused_kernel,
                         cudaFuncAttributeMaxDynamicSharedMemorySize,
                         (int)smem_bytes);
    fused_kernel<<<M_TOTAL / BM, 256, smem_bytes>>>(x, W, b, out);
}

// round 5
// speedup vs baseline: 3.7191x; 3.7191x over previous
#include <cuda_runtime.h>
#include <cuda_fp16.h>
#include <cstdint>

// Problem: x [8,256,256,256] fp32, W [256,256], b [256]
//   u = x[:,:128], v = x[:,128:]; per-batch LayerNorm(v); v@W^T+b; out=u*(v+1)
#define B_              8
#define WD              256
#define ROWS_PER_BATCH  32768
#define M_TOTAL         262144
#define NV              8388608
#define BATCH_STRIDE    (2 * NV)
#define NCHUNK          512
#define EPS             1e-5f

#define BM   128          // rows per CTA
#define KC   64           // K chunk

// SMEM map (dynamic, bytes)
#define SMEM_BIAS  0
#define SMEM_A0    1024
#define SMEM_A1    17408
#define SMEM_B     33792           // 256 o-rows x 512B (256 fp16 k)
#define SMEM_TOTAL 164864

// ---------------- device scratch ----------------
__device__ float g_partS[B_ * NCHUNK];
__device__ float g_partQ[B_ * NCHUNK];
__device__ float g_mean[B_];
__device__ float g_rstd[B_];
__device__ __half g_Wh[WD * WD];

// ---------------- helpers ----------------
__device__ __forceinline__ uint32_t smem_u32(const void* p) {
    uint32_t a;
    asm("{ .reg .u64 t; cvta.to.shared.u64 t, %1; cvt.u32.u64 %0, t; }"
        : "=r"(a) : "l"(p));
    return a;
}
// pack two fp32 -> f16x2 (lo arg in low half)
__device__ __forceinline__ uint32_t pack_f16x2(float lo, float hi) {
    uint32_t r;
    asm("cvt.rn.f16x2.f32 %0, %1, %2;" : "=r"(r) : "f"(hi), "f"(lo));
    return r;
}
__device__ __forceinline__ void ldsm_x4(uint32_t& r0, uint32_t& r1, uint32_t& r2,
                                        uint32_t& r3, uint32_t addr) {
    asm volatile("ldmatrix.sync.aligned.m8n8.x4.shared.b16 {%0,%1,%2,%3}, [%4];"
                 : "=r"(r0), "=r"(r1), "=r"(r2), "=r"(r3) : "r"(addr));
}
__device__ __forceinline__ void mma16816(float* d, const uint32_t* a,
                                         uint32_t b0, uint32_t b1) {
    asm volatile(
        "mma.sync.aligned.m16n8k16.row.col.f32.f16.f16.f32 "
        "{%0,%1,%2,%3}, {%4,%5,%6,%7}, {%8,%9}, {%0,%1,%2,%3};"
        : "+f"(d[0]), "+f"(d[1]), "+f"(d[2]), "+f"(d[3])
        : "r"(a[0]), "r"(a[1]), "r"(a[2]), "r"(a[3]), "r"(b0), "r"(b1));
}

// ---------------- W -> fp16 (tiny, once) ----------------
__global__ __launch_bounds__(256) void w_half_kernel(const float* __restrict__ W) {
    int i = blockIdx.x * 256 + threadIdx.x;
    g_Wh[i] = __float2half_rn(W[i]);
}

// ---------------- pass 1 / pass 2 (measured 76% DRAM) ----------------
__global__ __launch_bounds__(256) void reduce_pass1(const float* __restrict__ x) {
    const int b = blockIdx.y;
    const int chunk = blockIdx.x;
    const float4* v4 =
        reinterpret_cast<const float4*>(x + (size_t)b * BATCH_STRIDE + NV);
    const int base = chunk * 4096 + threadIdx.x;
    float s = 0.f, q = 0.f;
#pragma unroll
    for (int i = 0; i < 16; i++) {
        float4 t = v4[base + i * 256];
        s += (t.x + t.y) + (t.z + t.w);
        q += t.x * t.x + t.y * t.y + t.z * t.z + t.w * t.w;
    }
#pragma unroll
    for (int off = 16; off > 0; off >>= 1) {
        s += __shfl_xor_sync(0xffffffffu, s, off);
        q += __shfl_xor_sync(0xffffffffu, q, off);
    }
    __shared__ float ss[8], qs[8];
    const int warp = threadIdx.x >> 5, lane = threadIdx.x & 31;
    if (lane == 0) { ss[warp] = s; qs[warp] = q; }
    __syncthreads();
    if (threadIdx.x == 0) {
        float S = 0.f, Q = 0.f;
#pragma unroll
        for (int w = 0; w < 8; w++) { S += ss[w]; Q += qs[w]; }
        g_partS[b * NCHUNK + chunk] = S;
        g_partQ[b * NCHUNK + chunk] = Q;
    }
}

__global__ __launch_bounds__(256) void reduce_pass2() {
    const int b = blockIdx.x;
    float s = g_partS[b * NCHUNK + threadIdx.x] +
              g_partS[b * NCHUNK + 256 + threadIdx.x];
    float q = g_partQ[b * NCHUNK + threadIdx.x] +
              g_partQ[b * NCHUNK + 256 + threadIdx.x];
#pragma unroll
    for (int off = 16; off > 0; off >>= 1) {
        s += __shfl_xor_sync(0xffffffffu, s, off);
        q += __shfl_xor_sync(0xffffffffu, q, off);
    }
    __shared__ float ss[8], qs[8];
    const int warp = threadIdx.x >> 5, lane = threadIdx.x & 31;
    if (lane == 0) { ss[warp] = s; qs[warp] = q; }
    __syncthreads();
    if (threadIdx.x == 0) {
        float S = 0.f, Q = 0.f;
#pragma unroll
        for (int w = 0; w < 8; w++) { S += ss[w]; Q += qs[w]; }
        const float inv_n = 1.0f / (float)NV;
        float mean = S * inv_n;
        float var = Q * inv_n - mean * mean;
        g_mean[b] = mean;
        g_rstd[b] = rsqrtf(var + EPS);
    }
}

// ---------------- fused: normalize -> fp16 HMMA GEMM -> gating ----------------
// CTA: 128 rows x 256 outs, K=256. 8 warps, warp tile 64x64 (m16n8k16 grid 4x8).
// A chunks (128x64 fp16) double-buffered; whole W (256x256 fp16) smem-resident.
extern __shared__ char smc[];

__global__ __launch_bounds__(256, 1) void fused_kernel(
    const float* __restrict__ x, const float* __restrict__ bias,
    float* __restrict__ out) {
    const uint32_t sb = smem_u32(smc);
    const int t = threadIdx.x;
    const int wid = t >> 5, lane = t & 31;

    const int row0 = blockIdx.x * BM;
    const int batch = row0 >> 15;
    const int rlocal0 = row0 & (ROWS_PER_BATCH - 1);
    const float mean = g_mean[batch];
    const float rstd = g_rstd[batch];

    const float4* v4 = reinterpret_cast<const float4*>(
        x + (size_t)batch * BATCH_STRIDE + NV + (size_t)rlocal0 * WD);
    const uint4* Wh4 = reinterpret_cast<const uint4*>(g_Wh);

    // ---- stage bias ----
    if (t < 64)
        reinterpret_cast<float4*>(smc + SMEM_BIAS)[t] =
            reinterpret_cast<const float4*>(bias)[t];

    // ---- stage whole W into Bs [o][k] fp16, XOR-swizzled ----
#pragma unroll
    for (int it = 0; it < 32; it++) {
        int idx = it * 256 + t;          // 8192 x 16B
        int o = idx >> 5;
        int ku = idx & 31;               // 16B unit (8 fp16 of k)
        uint32_t off = (uint32_t)(o * 512 + ku * 16);
        off ^= (uint32_t)((o & 7) << 4);
        *reinterpret_cast<uint4*>(smc + SMEM_B + off) = Wh4[o * 32 + ku];
    }

    // ---- stage A chunk 0 ----
    {
        char* A0 = smc + SMEM_A0;
#pragma unroll
        for (int u_ = 0; u_ < 4; u_++) {
            int idx = u_ * 256 + t;      // 1024 units of 8 k
            int m = idx >> 3;
            int ku8 = idx & 7;
            float4 f0 = v4[m * 64 + ku8 * 2 + 0];
            float4 f1 = v4[m * 64 + ku8 * 2 + 1];
            uint4 val;
            val.x = pack_f16x2((f0.x - mean) * rstd, (f0.y - mean) * rstd);
            val.y = pack_f16x2((f0.z - mean) * rstd, (f0.w - mean) * rstd);
            val.z = pack_f16x2((f1.x - mean) * rstd, (f1.y - mean) * rstd);
            val.w = pack_f16x2((f1.z - mean) * rstd, (f1.w - mean) * rstd);
            uint32_t off = (uint32_t)(m * 128 + ku8 * 16);
            off ^= (uint32_t)((m & 7) << 4);
            *reinterpret_cast<uint4*>(A0 + off) = val;
        }
    }
    __syncthreads();

    // ---- mainloop ----
    const int wm = (wid >> 2) * 64;      // warp m base
    const int wn = (wid & 3) * 64;       // warp n base
    const int lg = lane >> 3, lr = lane & 7;

    float acc[4][8][4];
#pragma unroll
    for (int i = 0; i < 4; i++)
#pragma unroll
        for (int j = 0; j < 8; j++)
#pragma unroll
            for (int q = 0; q < 4; q++) acc[i][j][q] = 0.f;

#pragma unroll 1
    for (int c = 0; c < 4; c++) {
        const uint32_t Asb = sb + ((c & 1) ? SMEM_A1 : SMEM_A0);

        // prefetch next A chunk to regs
        float4 pf[8];
        if (c < 3) {
#pragma unroll
            for (int u_ = 0; u_ < 4; u_++) {
                int idx = u_ * 256 + t;
                int m = idx >> 3;
                int ku8 = idx & 7;
                pf[u_ * 2 + 0] = v4[m * 64 + (c + 1) * 16 + ku8 * 2 + 0];
                pf[u_ * 2 + 1] = v4[m * 64 + (c + 1) * 16 + ku8 * 2 + 1];
            }
        }

        // compute: 4 ksteps of 16
#pragma unroll
        for (int ks = 0; ks < 4; ks++) {
            const int kl = ks * 16;
            const int kg = c * 64 + kl;

            uint32_t af[4][4];
#pragma unroll
            for (int i = 0; i < 4; i++) {
                int am = wm + i * 16 + ((lg & 1) << 3) + lr;
                int ak = kl + ((lg >> 1) << 3);
                uint32_t off = (uint32_t)(am * 128 + ak * 2);
                off ^= (uint32_t)((am & 7) << 4);
                ldsm_x4(af[i][0], af[i][1], af[i][2], af[i][3], Asb + off);
            }
#pragma unroll
            for (int p = 0; p < 4; p++) {
                // non-trans ldmatrix on [n][k] tile: matrices along k give b0,b1
                int bn = wn + p * 16 + ((lg >> 1) << 3) + lr;
                int bk = kg + ((lg & 1) << 3);
                uint32_t off = (uint32_t)(bn * 512 + bk * 2);
                off ^= (uint32_t)((bn & 7) << 4);
                uint32_t b0, b1, b2, b3;
                ldsm_x4(b0, b1, b2, b3, sb + SMEM_B + off);
#pragma unroll
                for (int i = 0; i < 4; i++) {
                    mma16816(acc[i][p * 2 + 0], af[i], b0, b1);
                    mma16816(acc[i][p * 2 + 1], af[i], b2, b3);
                }
            }
        }

        // store prefetched chunk into other buffer
        if (c < 3) {
            char* An = smc + (((c + 1) & 1) ? SMEM_A1 : SMEM_A0);
#pragma unroll
            for (int u_ = 0; u_ < 4; u_++) {
                int idx = u_ * 256 + t;
                int m = idx >> 3;
                int ku8 = idx & 7;
                float4 f0 = pf[u_ * 2 + 0];
                float4 f1 = pf[u_ * 2 + 1];
                uint4 val;
                val.x = pack_f16x2((f0.x - mean) * rstd, (f0.y - mean) * rstd);
                val.y = pack_f16x2((f0.z - mean) * rstd, (f0.w - mean) * rstd);
                val.z = pack_f16x2((f1.x - mean) * rstd, (f1.y - mean) * rstd);
                val.w = pack_f16x2((f1.z - mean) * rstd, (f1.w - mean) * rstd);
                uint32_t off = (uint32_t)(m * 128 + ku8 * 16);
                off ^= (uint32_t)((m & 7) << 4);
                *reinterpret_cast<uint4*>(An + off) = val;
            }
            __syncthreads();
        }
    }

    // ---- epilogue: out = u * (acc + bias + 1) ----
    {
        const int qr = lane >> 2;
        const int qc = (lane & 3) * 2;
        const float* uBase =
            x + (size_t)batch * BATCH_STRIDE + (size_t)rlocal0 * WD;
        const float* bias_s = reinterpret_cast<const float*>(smc + SMEM_BIAS);
#pragma unroll
        for (int i = 0; i < 4; i++) {
#pragma unroll
            for (int half = 0; half < 2; half++) {
                const int lrow = wm + i * 16 + qr + half * 8;
                const float* up = uBase + (size_t)lrow * WD;
                float* op = out + (size_t)(row0 + lrow) * WD;
#pragma unroll
                for (int j = 0; j < 8; j++) {
                    const int col = wn + j * 8 + qc;
                    float2 u2 = *reinterpret_cast<const float2*>(up + col);
                    float2 b2 = *reinterpret_cast<const float2*>(bias_s + col);
                    float d0 = acc[i][j][half * 2 + 0];
                    float d1 = acc[i][j][half * 2 + 1];
                    float2 r;
                    r.x = u2.x * (d0 + b2.x + 1.f);
                    r.y = u2.y * (d1 + b2.y + 1.f);
                    *reinterpret_cast<float2*>(op + col) = r;
                }
            }
        }
    }
}

// ---------------- launch ----------------
extern "C" void kernel_launch(void* const* d_in, const int* in_sizes, int n_in,
                              void* d_out, int out_size) {
    const float* x = (const float*)d_in[0];
    const float* W = (const float*)d_in[1];
    const float* b = (const float*)d_in[2];
    float* out = (float*)d_out;

    w_half_kernel<<<WD * WD / 256, 256>>>(W);
    reduce_pass1<<<dim3(NCHUNK, B_), 256>>>(x);
    reduce_pass2<<<B_, 256>>>();

    cudaFuncSetAttribute(fused_kernel,
                         cudaFuncAttributeMaxDynamicSharedMemorySize, SMEM_TOTAL);
    fused_kernel<<<M_TOTAL / BM, 256, SMEM_TOTAL>>>(x, b, out);
}

// round 6
// speedup vs baseline: 3.8342x; 1.0309x over previous
#include <cuda_runtime.h>
#include <cuda_fp16.h>
#include <cstdint>

// Problem: x [8,256,256,256] fp32, W [256,256], b [256]
//   u = x[:,:128], v = x[:,128:]; per-batch LayerNorm(v); v@W^T+b; out=u*(v+1)
// LayerNorm deferred to epilogue: vnorm@W^T = rstd*(v@W^T) - mean*rstd*rowsum(W)
#define B_              8
#define WD              256
#define ROWS_PER_BATCH  32768
#define M_TOTAL         262144
#define NV              8388608
#define BATCH_STRIDE    (2 * NV)
#define NCHUNK          512
#define EPS             1e-5f

#define BM   128          // rows per CTA
#define KC   64           // K chunk
#define NT   512          // threads per CTA (16 warps)

// SMEM map (bytes): c1 coefs, A double buf (128x64 fp16), B double buf (256x64 fp16)
#define SMEM_C1    0
#define SMEM_A0    1024
#define SMEM_A1    (SMEM_A0 + 16384)
#define SMEM_B0    (SMEM_A1 + 16384)
#define SMEM_B1    (SMEM_B0 + 32768)
#define SMEM_TOTAL (SMEM_B1 + 32768)   // 99328

// ---------------- device scratch ----------------
__device__ float  g_partS[B_ * NCHUNK];
__device__ float  g_partQ[B_ * NCHUNK];
__device__ float  g_mean[B_];
__device__ float  g_rstd[B_];
__device__ float  g_Wsum[WD];
__device__ __half g_Wh[WD * WD];
__device__ __half g_vh[(size_t)M_TOTAL * WD];   // raw v, fp16 (written by pass1)

// ---------------- helpers ----------------
__device__ __forceinline__ uint32_t smem_u32(const void* p) {
    uint32_t a;
    asm("{ .reg .u64 t; cvta.to.shared.u64 t, %1; cvt.u32.u64 %0, t; }"
        : "=r"(a) : "l"(p));
    return a;
}
__device__ __forceinline__ uint32_t pack_f16x2(float lo, float hi) {
    uint32_t r;
    asm("cvt.rn.f16x2.f32 %0, %1, %2;" : "=r"(r) : "f"(hi), "f"(lo));
    return r;
}
__device__ __forceinline__ void cp16(uint32_t dst, const void* src) {
    asm volatile("cp.async.cg.shared.global [%0], [%1], 16;" :: "r"(dst), "l"(src));
}
#define CP_COMMIT() asm volatile("cp.async.commit_group;" ::: "memory")
#define CP_WAIT(n)  asm volatile("cp.async.wait_group %0;" :: "n"(n) : "memory")
__device__ __forceinline__ void ldsm_x4(uint32_t& r0, uint32_t& r1, uint32_t& r2,
                                        uint32_t& r3, uint32_t addr) {
    asm volatile("ldmatrix.sync.aligned.m8n8.x4.shared.b16 {%0,%1,%2,%3}, [%4];"
                 : "=r"(r0), "=r"(r1), "=r"(r2), "=r"(r3) : "r"(addr));
}
__device__ __forceinline__ void mma16816(float* d, const uint32_t* a,
                                         uint32_t b0, uint32_t b1) {
    asm volatile(
        "mma.sync.aligned.m16n8k16.row.col.f32.f16.f16.f32 "
        "{%0,%1,%2,%3}, {%4,%5,%6,%7}, {%8,%9}, {%0,%1,%2,%3};"
        : "+f"(d[0]), "+f"(d[1]), "+f"(d[2]), "+f"(d[3])
        : "r"(a[0]), "r"(a[1]), "r"(a[2]), "r"(a[3]), "r"(b0), "r"(b1));
}

// ---------------- W prep: fp16 convert + row sums (tiny) ----------------
__global__ __launch_bounds__(256) void w_prep_kernel(const float* __restrict__ W) {
    const int o = blockIdx.x, t = threadIdx.x;
    float w = W[o * WD + t];
    g_Wh[o * WD + t] = __float2half_rn(w);
    float s = w;
#pragma unroll
    for (int off = 16; off > 0; off >>= 1) s += __shfl_xor_sync(0xffffffffu, s, off);
    __shared__ float ss[8];
    if ((t & 31) == 0) ss[t >> 5] = s;
    __syncthreads();
    if (t == 0) {
        float S = 0.f;
#pragma unroll
        for (int w8 = 0; w8 < 8; w8++) S += ss[w8];
        g_Wsum[o] = S;
    }
}

// ---------------- pass 1: stats + v -> fp16 copy ----------------
__global__ __launch_bounds__(256) void reduce_pass1(const float* __restrict__ x) {
    const int b = blockIdx.y;
    const int chunk = blockIdx.x;
    const float4* v4 =
        reinterpret_cast<const float4*>(x + (size_t)b * BATCH_STRIDE + NV);
    uint2* vh2 = reinterpret_cast<uint2*>(g_vh + (size_t)b * NV);
    const int base = chunk * 4096 + threadIdx.x;
    float s = 0.f, q = 0.f;
#pragma unroll
    for (int i = 0; i < 16; i++) {
        float4 t = v4[base + i * 256];
        s += (t.x + t.y) + (t.z + t.w);
        q += t.x * t.x + t.y * t.y + t.z * t.z + t.w * t.w;
        vh2[base + i * 256] =
            make_uint2(pack_f16x2(t.x, t.y), pack_f16x2(t.z, t.w));
    }
#pragma unroll
    for (int off = 16; off > 0; off >>= 1) {
        s += __shfl_xor_sync(0xffffffffu, s, off);
        q += __shfl_xor_sync(0xffffffffu, q, off);
    }
    __shared__ float ss[8], qs[8];
    const int warp = threadIdx.x >> 5, lane = threadIdx.x & 31;
    if (lane == 0) { ss[warp] = s; qs[warp] = q; }
    __syncthreads();
    if (threadIdx.x == 0) {
        float S = 0.f, Q = 0.f;
#pragma unroll
        for (int w = 0; w < 8; w++) { S += ss[w]; Q += qs[w]; }
        g_partS[b * NCHUNK + chunk] = S;
        g_partQ[b * NCHUNK + chunk] = Q;
    }
}

__global__ __launch_bounds__(256) void reduce_pass2() {
    const int b = blockIdx.x;
    float s = g_partS[b * NCHUNK + threadIdx.x] +
              g_partS[b * NCHUNK + 256 + threadIdx.x];
    float q = g_partQ[b * NCHUNK + threadIdx.x] +
              g_partQ[b * NCHUNK + 256 + threadIdx.x];
#pragma unroll
    for (int off = 16; off > 0; off >>= 1) {
        s += __shfl_xor_sync(0xffffffffu, s, off);
        q += __shfl_xor_sync(0xffffffffu, q, off);
    }
    __shared__ float ss[8], qs[8];
    const int warp = threadIdx.x >> 5, lane = threadIdx.x & 31;
    if (lane == 0) { ss[warp] = s; qs[warp] = q; }
    __syncthreads();
    if (threadIdx.x == 0) {
        float S = 0.f, Q = 0.f;
#pragma unroll
        for (int w = 0; w < 8; w++) { S += ss[w]; Q += qs[w]; }
        const float inv_n = 1.0f / (float)NV;
        float mean = S * inv_n;
        float var = Q * inv_n - mean * mean;
        g_mean[b] = mean;
        g_rstd[b] = rsqrtf(var + EPS);
    }
}

// ---------------- fused GEMM + gating ----------------
// CTA 128x256, 16 warps (warp tile 32x64), K in 4 chunks of 64,
// A/B staged by cp.async into double-buffered XOR-swizzled tiles.
extern __shared__ char smc[];

__global__ __launch_bounds__(NT, 1) void fused_kernel(
    const float* __restrict__ x, const float* __restrict__ bias,
    float* __restrict__ out) {
    const uint32_t sb = smem_u32(smc);
    const int t = threadIdx.x;
    const int wid = t >> 5, lane = t & 31;

    const int row0 = blockIdx.x * BM;       // global row (g_vh is batch-flat)
    const int batch = row0 >> 15;
    const int rlocal0 = row0 & (ROWS_PER_BATCH - 1);
    const float mean = g_mean[batch];
    const float rstd = g_rstd[batch];

    // c1[o] = bias[o] + 1 - mean*rstd*Wsum[o]  (epilogue affine constant)
    if (t < WD) {
        float c = bias[t] + 1.f - mean * rstd * g_Wsum[t];
        reinterpret_cast<float*>(smc + SMEM_C1)[t] = c;
    }

    const char* vhp = reinterpret_cast<const char*>(g_vh + (size_t)row0 * WD);
    const char* whp = reinterpret_cast<const char*>(g_Wh);

    // stage chunk 0
    {
#pragma unroll
        for (int r = 0; r < 2; r++) {       // A: 1024 x 16B
            int idx = r * NT + t;
            int m = idx >> 3, ku = idx & 7;
            uint32_t off = (uint32_t)(m * 128 + ku * 16) ^ ((uint32_t)(m & 7) << 4);
            cp16(sb + SMEM_A0 + off, vhp + m * 512 + ku * 16);
        }
#pragma unroll
        for (int r = 0; r < 4; r++) {       // B: 2048 x 16B
            int idx = r * NT + t;
            int o = idx >> 3, ku = idx & 7;
            uint32_t off = (uint32_t)(o * 128 + ku * 16) ^ ((uint32_t)(o & 7) << 4);
            cp16(sb + SMEM_B0 + off, whp + o * 512 + ku * 16);
        }
        CP_COMMIT();
    }

    const int wm = (wid & 3) * 32;          // warp m base
    const int wn = (wid >> 2) * 64;         // warp n base
    const int lg = lane >> 3, lr = lane & 7;

    float acc[2][8][4];
#pragma unroll
    for (int i = 0; i < 2; i++)
#pragma unroll
        for (int j = 0; j < 8; j++)
#pragma unroll
            for (int q = 0; q < 4; q++) acc[i][j][q] = 0.f;

#pragma unroll 1
    for (int c = 0; c < 4; c++) {
        const uint32_t Ab = sb + ((c & 1) ? SMEM_A1 : SMEM_A0);
        const uint32_t Bb = sb + ((c & 1) ? SMEM_B1 : SMEM_B0);

        // issue next chunk into other buffer
        if (c < 3) {
            const uint32_t An = sb + (((c + 1) & 1) ? SMEM_A1 : SMEM_A0);
            const uint32_t Bn = sb + (((c + 1) & 1) ? SMEM_B1 : SMEM_B0);
            const int kb = (c + 1) * 128;   // byte offset of chunk in 512B row
#pragma unroll
            for (int r = 0; r < 2; r++) {
                int idx = r * NT + t;
                int m = idx >> 3, ku = idx & 7;
                uint32_t off = (uint32_t)(m * 128 + ku * 16) ^ ((uint32_t)(m & 7) << 4);
                cp16(An + off, vhp + m * 512 + kb + ku * 16);
            }
#pragma unroll
            for (int r = 0; r < 4; r++) {
                int idx = r * NT + t;
                int o = idx >> 3, ku = idx & 7;
                uint32_t off = (uint32_t)(o * 128 + ku * 16) ^ ((uint32_t)(o & 7) << 4);
                cp16(Bn + off, whp + o * 512 + kb + ku * 16);
            }
            CP_COMMIT();
            CP_WAIT(1);                     // chunk c complete
        } else {
            CP_WAIT(0);
        }
        __syncthreads();

        // compute chunk c: 4 ksteps of 16
#pragma unroll
        for (int ks = 0; ks < 4; ks++) {
            const int kl = ks * 16;
            uint32_t af[2][4];
#pragma unroll
            for (int i = 0; i < 2; i++) {
                int am = wm + i * 16 + ((lg & 1) << 3) + lr;
                int ak = kl + ((lg >> 1) << 3);
                uint32_t off = (uint32_t)(am * 128 + ak * 2) ^ ((uint32_t)(am & 7) << 4);
                ldsm_x4(af[i][0], af[i][1], af[i][2], af[i][3], Ab + off);
            }
#pragma unroll
            for (int p = 0; p < 4; p++) {
                int bn = wn + p * 16 + ((lg >> 1) << 3) + lr;
                int bk = kl + ((lg & 1) << 3);
                uint32_t off = (uint32_t)(bn * 128 + bk * 2) ^ ((uint32_t)(bn & 7) << 4);
                uint32_t b0, b1, b2, b3;
                ldsm_x4(b0, b1, b2, b3, Bb + off);
#pragma unroll
                for (int i = 0; i < 2; i++) {
                    mma16816(acc[i][p * 2 + 0], af[i], b0, b1);
                    mma16816(acc[i][p * 2 + 1], af[i], b2, b3);
                }
            }
        }
        __syncthreads();   // protect buffer before next-next issue overwrites
    }

    // epilogue: out = u * (acc*rstd + c1[o])
    {
        const int qr = lane >> 2;
        const int qc = (lane & 3) * 2;
        const float* uBase =
            x + (size_t)batch * BATCH_STRIDE + (size_t)rlocal0 * WD;
        const float* c1 = reinterpret_cast<const float*>(smc + SMEM_C1);
#pragma unroll
        for (int i = 0; i < 2; i++) {
#pragma unroll
            for (int half = 0; half < 2; half++) {
                const int lrow = wm + i * 16 + qr + half * 8;
                const float* up = uBase + (size_t)lrow * WD;
                float* op = out + (size_t)(row0 + lrow) * WD;
#pragma unroll
                for (int j = 0; j < 8; j++) {
                    const int col = wn + j * 8 + qc;
                    float2 u2 = *reinterpret_cast<const float2*>(up + col);
                    float2 cc = *reinterpret_cast<const float2*>(c1 + col);
                    float d0 = acc[i][j][half * 2 + 0];
                    float d1 = acc[i][j][half * 2 + 1];
                    float2 r;
                    r.x = u2.x * fmaf(d0, rstd, cc.x);
                    r.y = u2.y * fmaf(d1, rstd, cc.y);
                    *reinterpret_cast<float2*>(op + col) = r;
                }
            }
        }
    }
}

// ---------------- launch ----------------
extern "C" void kernel_launch(void* const* d_in, const int* in_sizes, int n_in,
                              void* d_out, int out_size) {
    const float* x = (const float*)d_in[0];
    const float* W = (const float*)d_in[1];
    const float* b = (const float*)d_in[2];
    float* out = (float*)d_out;

    w_prep_kernel<<<WD, 256>>>(W);
    reduce_pass1<<<dim3(NCHUNK, B_), 256>>>(x);
    reduce_pass2<<<B_, 256>>>();

    cudaFuncSetAttribute(fused_kernel,
                         cudaFuncAttributeMaxDynamicSharedMemorySize, SMEM_TOTAL);
    fused_kernel<<<M_TOTAL / BM, NT, SMEM_TOTAL>>>(x, b, out);
}

// round 8
// speedup vs baseline: 4.1030x; 1.0701x over previous
#include <cuda_runtime.h>
#include <cuda_fp16.h>
#include <cstdint>

// Problem: x [8,256,256,256] fp32, W [256,256], b [256]
//   u = x[:,:128], v = x[:,128:]; per-batch LayerNorm(v); v@W^T+b; out=u*(v+1)
// LayerNorm deferred to epilogue: vnorm@W^T = rstd*(v@W^T) - mean*rstd*rowsum(W)
#define B_              8
#define WD              256
#define ROWS_PER_BATCH  32768
#define M_TOTAL         262144
#define NV              8388608
#define BATCH_STRIDE    (2 * NV)
#define NCHUNK          512
#define EPS             1e-5f

#define BM   128          // rows per CTA
#define BN   128          // cols per CTA (half of WD)
#define NT   256          // 8 warps

// SMEM (bytes): c1 (128 floats), A 3-stage (128x64 fp16 each), B resident (128x256 fp16)
#define SMEM_C1    0
#define SMEM_A(s)  (1024 + (s) * 16384)
#define SMEM_B     (1024 + 3 * 16384)
#define SMEM_TOTAL (SMEM_B + 65536)      // 115712; x2 CTAs = full 228KB SM carveout

// ---------------- device scratch ----------------
__device__ float  g_partS[B_ * NCHUNK];
__device__ float  g_partQ[B_ * NCHUNK];
__device__ float  g_mean[B_];
__device__ float  g_rstd[B_];
__device__ float  g_Wsum[WD];
__device__ __half g_Wh[WD * WD];
__device__ __half g_vh[(size_t)M_TOTAL * WD];   // raw v, fp16 (written by pass1)

// ---------------- helpers ----------------
__device__ __forceinline__ uint32_t smem_u32(const void* p) {
    uint32_t a;
    asm("{ .reg .u64 t; cvta.to.shared.u64 t, %1; cvt.u32.u64 %0, t; }"
        : "=r"(a) : "l"(p));
    return a;
}
__device__ __forceinline__ uint32_t pack_f16x2(float lo, float hi) {
    uint32_t r;
    asm("cvt.rn.f16x2.f32 %0, %1, %2;" : "=r"(r) : "f"(hi), "f"(lo));
    return r;
}
__device__ __forceinline__ void cp16(uint32_t dst, const void* src) {
    asm volatile("cp.async.cg.shared.global [%0], [%1], 16;" :: "r"(dst), "l"(src));
}
#define CP_COMMIT() asm volatile("cp.async.commit_group;" ::: "memory")
#define CP_WAIT(n)  asm volatile("cp.async.wait_group %0;" :: "n"(n) : "memory")
__device__ __forceinline__ void ldsm_x4(uint32_t& r0, uint32_t& r1, uint32_t& r2,
                                        uint32_t& r3, uint32_t addr) {
    asm volatile("ldmatrix.sync.aligned.m8n8.x4.shared.b16 {%0,%1,%2,%3}, [%4];"
                 : "=r"(r0), "=r"(r1), "=r"(r2), "=r"(r3) : "r"(addr));
}
__device__ __forceinline__ void mma16816(float* d, const uint32_t* a,
                                         uint32_t b0, uint32_t b1) {
    asm volatile(
        "mma.sync.aligned.m16n8k16.row.col.f32.f16.f16.f32 "
        "{%0,%1,%2,%3}, {%4,%5,%6,%7}, {%8,%9}, {%0,%1,%2,%3};"
        : "+f"(d[0]), "+f"(d[1]), "+f"(d[2]), "+f"(d[3])
        : "r"(a[0]), "r"(a[1]), "r"(a[2]), "r"(a[3]), "r"(b0), "r"(b1));
}

// ---------------- W prep: fp16 convert + row sums (tiny) ----------------
__global__ __launch_bounds__(256) void w_prep_kernel(const float* __restrict__ W) {
    const int o = blockIdx.x, t = threadIdx.x;
    float w = W[o * WD + t];
    g_Wh[o * WD + t] = __float2half_rn(w);
    float s = w;
#pragma unroll
    for (int off = 16; off > 0; off >>= 1) s += __shfl_xor_sync(0xffffffffu, s, off);
    __shared__ float ss[8];
    if ((t & 31) == 0) ss[t >> 5] = s;
    __syncthreads();
    if (t == 0) {
        float S = 0.f;
#pragma unroll
        for (int w8 = 0; w8 < 8; w8++) S += ss[w8];
        g_Wsum[o] = S;
    }
}

// ---------------- pass 1: stats + v -> fp16 copy ----------------
__global__ __launch_bounds__(256) void reduce_pass1(const float* __restrict__ x) {
    const int b = blockIdx.y;
    const int chunk = blockIdx.x;
    const float4* v4 =
        reinterpret_cast<const float4*>(x + (size_t)b * BATCH_STRIDE + NV);
    uint2* vh2 = reinterpret_cast<uint2*>(g_vh + (size_t)b * NV);
    const int base = chunk * 4096 + threadIdx.x;
    float s = 0.f, q = 0.f;
#pragma unroll
    for (int i = 0; i < 16; i++) {
        float4 t = v4[base + i * 256];
        s += (t.x + t.y) + (t.z + t.w);
        q += t.x * t.x + t.y * t.y + t.z * t.z + t.w * t.w;
        vh2[base + i * 256] =
            make_uint2(pack_f16x2(t.x, t.y), pack_f16x2(t.z, t.w));
    }
#pragma unroll
    for (int off = 16; off > 0; off >>= 1) {
        s += __shfl_xor_sync(0xffffffffu, s, off);
        q += __shfl_xor_sync(0xffffffffu, q, off);
    }
    __shared__ float ss[8], qs[8];
    const int warp = threadIdx.x >> 5, lane = threadIdx.x & 31;
    if (lane == 0) { ss[warp] = s; qs[warp] = q; }
    __syncthreads();
    if (threadIdx.x == 0) {
        float S = 0.f, Q = 0.f;
#pragma unroll
        for (int w = 0; w < 8; w++) { S += ss[w]; Q += qs[w]; }
        g_partS[b * NCHUNK + chunk] = S;
        g_partQ[b * NCHUNK + chunk] = Q;
    }
}

__global__ __launch_bounds__(256) void reduce_pass2() {
    const int b = blockIdx.x;
    float s = g_partS[b * NCHUNK + threadIdx.x] +
              g_partS[b * NCHUNK + 256 + threadIdx.x];
    float q = g_partQ[b * NCHUNK + threadIdx.x] +
              g_partQ[b * NCHUNK + 256 + threadIdx.x];
#pragma unroll
    for (int off = 16; off > 0; off >>= 1) {
        s += __shfl_xor_sync(0xffffffffu, s, off);
        q += __shfl_xor_sync(0xffffffffu, q, off);
    }
    __shared__ float ss[8], qs[8];
    const int warp = threadIdx.x >> 5, lane = threadIdx.x & 31;
    if (lane == 0) { ss[warp] = s; qs[warp] = q; }
    __syncthreads();
    if (threadIdx.x == 0) {
        float S = 0.f, Q = 0.f;
#pragma unroll
        for (int w = 0; w < 8; w++) { S += ss[w]; Q += qs[w]; }
        const float inv_n = 1.0f / (float)NV;
        float mean = S * inv_n;
        float var = Q * inv_n - mean * mean;
        g_mean[b] = mean;
        g_rstd[b] = rsqrtf(var + EPS);
    }
}

// ---------------- fused GEMM + gating ----------------
// CTA 128x128, 8 warps (warp tile 32x64), 2 CTAs/SM.
// B (W half, 64KB) smem-resident; A 3-stage cp.async pipeline, 1 sync/chunk.
extern __shared__ char smc[];

__global__ __launch_bounds__(NT, 2) void fused_kernel(
    const float* __restrict__ x, const float* __restrict__ bias,
    float* __restrict__ out) {
    const uint32_t sb = smem_u32(smc);
    const int t = threadIdx.x;
    const int wid = t >> 5, lane = t & 31;

    const int nb = blockIdx.x;              // 0/1: which 128-col half of W
    const int row0 = blockIdx.y * BM;
    const int batch = row0 >> 15;
    const int rlocal0 = row0 & (ROWS_PER_BATCH - 1);
    const float mean = g_mean[batch];
    const float rstd = g_rstd[batch];

    const char* vhp = reinterpret_cast<const char*>(g_vh + (size_t)row0 * WD);
    const char* whp =
        reinterpret_cast<const char*>(g_Wh + (size_t)(nb * BN) * WD);

    // c1[o] = bias[o] + 1 - mean*rstd*Wsum[o]
    if (t < BN) {
        int col = nb * BN + t;
        reinterpret_cast<float*>(smc + SMEM_C1)[t] =
            bias[col] + 1.f - mean * rstd * g_Wsum[col];
    }

    // group 0: B resident (4096 x 16B) + A chunk 0 (1024 x 16B)
#pragma unroll
    for (int r = 0; r < 16; r++) {
        int idx = r * NT + t;
        int o = idx >> 5, ku = idx & 31;    // 512B rows (k=256)
        uint32_t off = (uint32_t)(o * 512 + ku * 16) ^ ((uint32_t)(o & 7) << 4);
        cp16(sb + SMEM_B + off, whp + o * 512 + ku * 16);
    }
#pragma unroll
    for (int r = 0; r < 4; r++) {
        int idx = r * NT + t;
        int m = idx >> 3, ku = idx & 7;     // 128B rows (k=64)
        uint32_t off = (uint32_t)(m * 128 + ku * 16) ^ ((uint32_t)(m & 7) << 4);
        cp16(sb + SMEM_A(0) + off, vhp + m * 512 + ku * 16);
    }
    CP_COMMIT();
    // group 1: A chunk 1
#pragma unroll
    for (int r = 0; r < 4; r++) {
        int idx = r * NT + t;
        int m = idx >> 3, ku = idx & 7;
        uint32_t off = (uint32_t)(m * 128 + ku * 16) ^ ((uint32_t)(m & 7) << 4);
        cp16(sb + SMEM_A(1) + off, vhp + m * 512 + 128 + ku * 16);
    }
    CP_COMMIT();

    const int wm = (wid & 3) * 32;          // warp m base (4 warps)
    const int wn = (wid >> 2) * 64;         // warp n base (2 warps)
    const int lg = lane >> 3, lr = lane & 7;

    float acc[2][8][4];
#pragma unroll
    for (int i = 0; i < 2; i++)
#pragma unroll
        for (int j = 0; j < 8; j++)
#pragma unroll
            for (int q = 0; q < 4; q++) acc[i][j][q] = 0.f;

#pragma unroll 1
    for (int c = 0; c < 4; c++) {
        if (c < 3) CP_WAIT(1); else CP_WAIT(0);
        __syncthreads();   // all warps done with buffer (c-1)%3 and chunk c ready

        // issue chunk c+2 into stage (c+2)%3 (drained by the sync above)
        if (c < 2) {
            const uint32_t An = sb + SMEM_A((c + 2) % 3);
            const int kb = (c + 2) * 128;
#pragma unroll
            for (int r = 0; r < 4; r++) {
                int idx = r * NT + t;
                int m = idx >> 3, ku = idx & 7;
                uint32_t off = (uint32_t)(m * 128 + ku * 16) ^ ((uint32_t)(m & 7) << 4);
                cp16(An + off, vhp + m * 512 + kb + ku * 16);
            }
            CP_COMMIT();
        }

        // compute chunk c from stage c%3
        const uint32_t Ab = sb + SMEM_A(c % 3);
#pragma unroll
        for (int ks = 0; ks < 4; ks++) {
            const int kl = ks * 16;
            uint32_t af[2][4];
#pragma unroll
            for (int i = 0; i < 2; i++) {
                int am = wm + i * 16 + ((lg & 1) << 3) + lr;
                int ak = kl + ((lg >> 1) << 3);
                uint32_t off = (uint32_t)(am * 128 + ak * 2) ^ ((uint32_t)(am & 7) << 4);
                ldsm_x4(af[i][0], af[i][1], af[i][2], af[i][3], Ab + off);
            }
#pragma unroll
            for (int p = 0; p < 4; p++) {
                int bn = wn + p * 16 + ((lg >> 1) << 3) + lr;
                int bk = c * 64 + kl + ((lg & 1) << 3);
                uint32_t off = (uint32_t)(bn * 512 + bk * 2) ^ ((uint32_t)(bn & 7) << 4);
                uint32_t b0, b1, b2, b3;
                ldsm_x4(b0, b1, b2, b3, sb + SMEM_B + off);
#pragma unroll
                for (int i = 0; i < 2; i++) {
                    mma16816(acc[i][p * 2 + 0], af[i], b0, b1);
                    mma16816(acc[i][p * 2 + 1], af[i], b2, b3);
                }
            }
        }
    }

    // epilogue: out = u * (acc*rstd + c1[col])
    {
        const int qr = lane >> 2;
        const int qc = (lane & 3) * 2;
        const int colbase = nb * BN;
        const float* uBase =
            x + (size_t)batch * BATCH_STRIDE + (size_t)rlocal0 * WD + colbase;
        const float* c1 = reinterpret_cast<const float*>(smc + SMEM_C1);
#pragma unroll
        for (int i = 0; i < 2; i++) {
#pragma unroll
            for (int half = 0; half < 2; half++) {
                const int lrow = wm + i * 16 + qr + half * 8;
                const float* up = uBase + (size_t)lrow * WD;
                float* op = out + (size_t)(row0 + lrow) * WD + colbase;
#pragma unroll
                for (int j = 0; j < 8; j++) {
                    const int col = wn + j * 8 + qc;
                    float2 u2 = *reinterpret_cast<const float2*>(up + col);
                    float2 cc = *reinterpret_cast<const float2*>(c1 + col);
                    float d0 = acc[i][j][half * 2 + 0];
                    float d1 = acc[i][j][half * 2 + 1];
                    float2 r;
                    r.x = u2.x * fmaf(d0, rstd, cc.x);
                    r.y = u2.y * fmaf(d1, rstd, cc.y);
                    *reinterpret_cast<float2*>(op + col) = r;
                }
            }
        }
    }
}

// ---------------- launch ----------------
extern "C" void kernel_launch(void* const* d_in, const int* in_sizes, int n_in,
                              void* d_out, int out_size) {
    const float* x = (const float*)d_in[0];
    const float* W = (const float*)d_in[1];
    const float* b = (const float*)d_in[2];
    float* out = (float*)d_out;

    w_prep_kernel<<<WD, 256>>>(W);
    reduce_pass1<<<dim3(NCHUNK, B_), 256>>>(x);
    reduce_pass2<<<B_, 256>>>();

    cudaFuncSetAttribute(fused_kernel,
                         cudaFuncAttributeMaxDynamicSharedMemorySize, SMEM_TOTAL);
    fused_kernel<<<dim3(2, M_TOTAL / BM), NT, SMEM_TOTAL>>>(x, b, out);
}